// round 8
// baseline (speedup 1.0000x reference)
#include <cuda_runtime.h>
#include <math.h>

#define B_    32
#define INC_  10
#define LIN_  16384
#define CH_   20
#define NPOLY 12
#define MM_   6
#define NB_   4
// lengths: l0=16434 -> 16422,16410,16398,16386 (all divisible by 6)

#define BUFN 10520000  // >= 32*20*16434

__device__ float g_xa[BUFN];
__device__ float g_xb[BUFN];
__device__ float g_y1[BUFN];
__device__ float g_y2[BUFN];

typedef unsigned long long ull;

__device__ __forceinline__ ull pk2(float lo, float hi) {
    ull r; asm("mov.b64 %0, {%1, %2};" : "=l"(r) : "f"(lo), "f"(hi)); return r;
}
__device__ __forceinline__ void upk2(ull v, float& lo, float& hi) {
    asm("mov.b64 {%0, %1}, %2;" : "=f"(lo), "=f"(hi) : "l"(v));
}
__device__ __forceinline__ ull fma2(ull a, ull b, ull c) {
    ull d; asm("fma.rn.f32x2 %0, %1, %2, %3;" : "=l"(d) : "l"(a), "l"(b), "l"(c));
    return d;
}

// Branchless gelu: Abramowitz-Stegun 7.1.26 erf approx (|abs err| < 1.5e-7)
__device__ __forceinline__ float gelu_f(float x) {
    float z = 0.7071067811865476f * x;
    float s = fabsf(z);
    float t = __fdividef(1.0f, fmaf(0.3275911f, s, 1.0f));
    float p = fmaf(fmaf(fmaf(fmaf(1.061405429f, t, -1.453152027f),
                             t, 1.421413741f), t, -0.284496736f), t, 0.254829592f) * t;
    float e = __expf(-s * s);
    float er = fmaf(-p, e, 1.0f);
    er = copysignf(er, z);
    return 0.5f * x * (1.0f + er);
}

// ---------------------------------------------------------------------------
// First conv: input (B,10,16384) wrap-padded (25,27), conv3 -> (B,20,16434)
// ---------------------------------------------------------------------------
__global__ void __launch_bounds__(128) k_first(
    const float* __restrict__ in, const float* __restrict__ w,
    float* __restrict__ out, int lout)
{
    __shared__ float sw[CH_ * INC_ * 3];
    int tid = threadIdx.x;
    for (int i = tid; i < CH_ * INC_ * 3; i += blockDim.x) sw[i] = w[i];
    __syncthreads();

    int b = blockIdx.y;
    int t = blockIdx.x * blockDim.x + tid;
    if (t >= lout) return;

    int base = t - 25;
    int i0 = base;     if (i0 < 0) i0 += LIN_; else if (i0 >= LIN_) i0 -= LIN_;
    int i1 = base + 1; if (i1 < 0) i1 += LIN_; else if (i1 >= LIN_) i1 -= LIN_;
    int i2 = base + 2; if (i2 < 0) i2 += LIN_; else if (i2 >= LIN_) i2 -= LIN_;

    const float* inb = in + (size_t)b * INC_ * LIN_;
    float acc[CH_];
#pragma unroll
    for (int co = 0; co < CH_; co++) acc[co] = 0.f;
#pragma unroll
    for (int ci = 0; ci < INC_; ci++) {
        float v0 = inb[ci * LIN_ + i0];
        float v1 = inb[ci * LIN_ + i1];
        float v2 = inb[ci * LIN_ + i2];
#pragma unroll
        for (int co = 0; co < CH_; co++) {
            const float* wp = sw + (co * INC_ + ci) * 3;
            acc[co] = fmaf(wp[0], v0, fmaf(wp[1], v1, fmaf(wp[2], v2, acc[co])));
        }
    }
    float* ob = out + (size_t)b * CH_ * lout;
#pragma unroll
    for (int co = 0; co < CH_; co++) ob[co * lout + t] = acc[co];
}

// ---------------------------------------------------------------------------
// conv3 20->20 VALID, smem-staged x, optional gelu.
// Tile: 128 outputs/block. 4 warps x 5 co each; VT=4 consecutive t per thread.
// x taps via 3 conflict-free LDS.64 (j0 = 4*lane even, row stride 132 even).
// Weights: 15 broadcast LDS per warp-ci, hoisted over 60 FMA.
// Stores: 2x STG.64 per co (row stride lout is even but not mult of 4).
// ---------------------------------------------------------------------------
#define CXROW 132   // row stride: >= 130, even

template <bool DO_GELU>
__global__ void __launch_bounds__(128) k_conv_s(
    const float* __restrict__ x, const float* __restrict__ w,
    float* __restrict__ out, int lin)
{
    __shared__ __align__(16) float xs[CH_][CXROW];
    __shared__ float sw[CH_ * CH_ * 3];

    int tid = threadIdx.x;
    int b = blockIdx.y;
    int T0 = blockIdx.x * 128;
    int lout = lin - 2;

    for (int i = tid; i < CH_ * CH_ * 3; i += 128) sw[i] = w[i];
    for (int i = tid; i < CH_ * 130; i += 128) {
        int ci = i / 130, j = i % 130;
        int gp = T0 + j;
        xs[ci][j] = (gp < lin) ? x[((size_t)b * CH_ + ci) * lin + gp] : 0.f;
    }
    __syncthreads();

    int wq = tid >> 5, lane = tid & 31;
    int cob = 5 * wq;
    int j0 = 4 * lane;

    float a[5][4];
#pragma unroll
    for (int cc = 0; cc < 5; cc++)
#pragma unroll
        for (int e = 0; e < 4; e++) a[cc][e] = 0.f;

#pragma unroll
    for (int ci = 0; ci < CH_; ci++) {
        float wr[15];
#pragma unroll
        for (int cc = 0; cc < 5; cc++)
#pragma unroll
            for (int k = 0; k < 3; k++)
                wr[cc * 3 + k] = sw[((cob + cc) * CH_ + ci) * 3 + k];

        float2 A  = *(const float2*)&xs[ci][j0];      // x[j0], x[j0+1]
        float2 Bv = *(const float2*)&xs[ci][j0 + 2];  // x[j0+2], x[j0+3]
        float2 Cv = *(const float2*)&xs[ci][j0 + 4];  // x[j0+4], x[j0+5]
        float x0 = A.x, x1 = A.y, x2 = Bv.x, x3 = Bv.y, x4 = Cv.x, x5 = Cv.y;

#pragma unroll
        for (int cc = 0; cc < 5; cc++) {
            float w0 = wr[cc * 3], w1 = wr[cc * 3 + 1], w2 = wr[cc * 3 + 2];
            a[cc][0] = fmaf(w0, x0, fmaf(w1, x1, fmaf(w2, x2, a[cc][0])));
            a[cc][1] = fmaf(w0, x1, fmaf(w1, x2, fmaf(w2, x3, a[cc][1])));
            a[cc][2] = fmaf(w0, x2, fmaf(w1, x3, fmaf(w2, x4, a[cc][2])));
            a[cc][3] = fmaf(w0, x3, fmaf(w1, x4, fmaf(w2, x5, a[cc][3])));
        }
    }

    int t = T0 + j0;
    if (t + 3 < lout) {
#pragma unroll
        for (int cc = 0; cc < 5; cc++) {
            float u0 = a[cc][0], u1 = a[cc][1], u2 = a[cc][2], u3 = a[cc][3];
            if (DO_GELU) { u0 = gelu_f(u0); u1 = gelu_f(u1); u2 = gelu_f(u2); u3 = gelu_f(u3); }
            float* op = &out[((size_t)b * CH_ + cob + cc) * lout + t];
            *(float2*)op       = make_float2(u0, u1);
            *(float2*)(op + 2) = make_float2(u2, u3);
        }
    } else if (t < lout) {
#pragma unroll
        for (int cc = 0; cc < 5; cc++) {
            float* op = &out[((size_t)b * CH_ + cob + cc) * lout];
#pragma unroll
            for (int e = 0; e < 4; e++) {
                if (t + e < lout) {
                    float u = a[cc][e];
                    if (DO_GELU) u = gelu_f(u);
                    op[t + e] = u;
                }
            }
        }
    }
}

// ---------------------------------------------------------------------------
// Legendre decomposition + cross-channel block-diag mixing (R2 version, exact).
// ---------------------------------------------------------------------------
#define TB_ 32
__global__ void __launch_bounds__(640) k_legmix(
    const float* __restrict__ x, const float* __restrict__ lm_g,
    const float* __restrict__ fd, float* __restrict__ Lg, int lin, int ll)
{
    __shared__ float xs[CH_][TB_ * 6 + 6];   // 20 x 198
    __shared__ float fd2[MM_ * NPOLY];
    __shared__ float lm[CH_ * MM_ * MM_];

    int b = blockIdx.y;
    int T0 = blockIdx.x * TB_;
    int tid = threadIdx.y * TB_ + threadIdx.x;

    for (int i = tid; i < MM_ * NPOLY; i += 640) fd2[i] = 0.5f * fd[i];
    for (int i = tid; i < CH_ * MM_ * MM_; i += 640) lm[i] = lm_g[i];
    for (int i = tid; i < CH_ * (TB_ * 6 + 6); i += 640) {
        int ci = i / (TB_ * 6 + 6);
        int j  = i % (TB_ * 6 + 6);
        int pos = 6 * T0 + j;
        xs[ci][j] = (pos < lin) ? x[((size_t)b * CH_ + ci) * lin + pos] : 0.f;
    }
    __syncthreads();

    int tloc = threadIdx.x;
    int g = threadIdx.y;
    int t = T0 + tloc;
    if (t >= ll) return;

    float v[MM_];
#pragma unroll
    for (int i = 0; i < MM_; i++) {
        int q  = 6 * g + i;
        int mi = q / CH_;
        int ci = q % CH_;
        float s = 0.f;
#pragma unroll
        for (int k = 0; k < NPOLY; k++)
            s = fmaf(fd2[mi * NPOLY + k], xs[ci][6 * tloc + k], s);
        v[i] = s;
    }
#pragma unroll
    for (int o = 0; o < MM_; o++) {
        float s = 0.f;
#pragma unroll
        for (int i = 0; i < MM_; i++)
            s = fmaf(lm[(g * MM_ + o) * MM_ + i], v[i], s);
        int p  = 6 * g + o;
        int mo = p / CH_;
        int co = p % CH_;
        Lg[(((size_t)b * MM_ + mo) * CH_ + co) * ll + t] = s;
    }
}

// ---------------------------------------------------------------------------
// Overlap-add reconstruction + residual + gelu, VT=6 (R7 version, validated).
// ---------------------------------------------------------------------------
__global__ void __launch_bounds__(128) k_recon(
    const float* __restrict__ Lg, const float* __restrict__ fr,
    const float* __restrict__ y2, float* __restrict__ out, int ll, int lout)
{
    __shared__ float sfr[MM_ * NPOLY];
    __shared__ float sbuf[128 * 6];

    int tid = threadIdx.x;
    if (tid < MM_ * NPOLY) sfr[tid] = fr[tid];
    __syncthreads();

    int bc = blockIdx.y;
    int b = bc / CH_, co = bc % CH_;
    int nu = lout / 6;

    int u = blockIdx.x * 128 + tid;
    if (u < nu) {
        int t0 = u + 1;
        const float* Lo = Lg + (((size_t)b * MM_) * CH_ + co) * ll;
        size_t mstride = (size_t)CH_ * ll;
        float rec[6];
#pragma unroll
        for (int e = 0; e < 6; e++) rec[e] = 0.f;
#pragma unroll
        for (int m = 0; m < MM_; m++) {
            float uc = Lo[m * mstride + t0];
            float up = Lo[m * mstride + t0 - 1];
#pragma unroll
            for (int e = 0; e < 6; e++) {
                rec[e] = fmaf(uc, sfr[m * NPOLY + e],     rec[e]);
                rec[e] = fmaf(up, sfr[m * NPOLY + e + 6], rec[e]);
            }
        }
#pragma unroll
        for (int e = 0; e < 6; e++) sbuf[6 * tid + e] = rec[e];
    }
    __syncthreads();

    int Tbase = blockIdx.x * 768;
    int liny2 = lout + 8;
    const float* y2r = y2 + (size_t)bc * liny2;
    float* outr = out + (size_t)bc * lout;
#pragma unroll
    for (int e2 = 0; e2 < 6; e2++) {
        int idx = tid + 128 * e2;
        int t = Tbase + idx;
        if (t < lout)
            outr[t] = gelu_f(sbuf[idx] + y2r[t + 4]);
    }
}

// ---------------------------------------------------------------------------
// Final 20->128(gelu)->1 with f32x2, VT=4 (validated).
// ---------------------------------------------------------------------------
__global__ void __launch_bounds__(128) k_final_f2(
    const float* __restrict__ x, const float* __restrict__ w11,
    const float* __restrict__ w_out, float* __restrict__ out, int lin)
{
    __shared__ __align__(16) float2 swd[128 * CH_];
    __shared__ float so[128];
    int tid = threadIdx.x;
    for (int i = tid; i < 128 * CH_; i += 128) {
        float v = w11[i];
        swd[i] = make_float2(v, v);
    }
    if (tid < 128) so[tid] = w_out[tid];
    __syncthreads();

    int b = blockIdx.y;
    int t0 = (blockIdx.x * 128 + tid) * 4;
    if (t0 >= LIN_) return;

    const float* xb = x + (size_t)b * CH_ * lin + t0;
    ull xv01[CH_], xv23[CH_];
#pragma unroll
    for (int c = 0; c < CH_; c++) {
        const float* xp = xb + c * lin;
        xv01[c] = pk2(xp[0], xp[1]);
        xv23[c] = pk2(xp[2], xp[3]);
    }

    ull zero = pk2(0.f, 0.f);
    ull acc01 = zero, acc23 = zero;
#pragma unroll 2
    for (int o = 0; o < 128; o++) {
        ull h01 = zero, h23 = zero;
#pragma unroll
        for (int c = 0; c < CH_; c++) {
            ull wv = *(const ull*)&swd[o * CH_ + c];
            h01 = fma2(wv, xv01[c], h01);
            h23 = fma2(wv, xv23[c], h23);
        }
        float h0, h1, h2, h3;
        upk2(h01, h0, h1); upk2(h23, h2, h3);
        float ov = so[o];
        ull ov2 = pk2(ov, ov);
        acc01 = fma2(ov2, pk2(gelu_f(h0), gelu_f(h1)), acc01);
        acc23 = fma2(ov2, pk2(gelu_f(h2), gelu_f(h3)), acc23);
    }
    float r0, r1, r2, r3;
    upk2(acc01, r0, r1); upk2(acc23, r2, r3);
    float4* op = (float4*)&out[(size_t)b * LIN_ + t0];
    *op = make_float4(r0, r1, r2, r3);
}

// ---------------------------------------------------------------------------
extern "C" void kernel_launch(void* const* d_in, const int* in_sizes, int n_in,
                              void* d_out, int out_size)
{
    const float* input  = (const float*)d_in[0];
    const float* w_first= (const float*)d_in[1];
    const float* conv_a = (const float*)d_in[2];
    const float* conv_b = (const float*)d_in[3];
    const float* lin_m  = (const float*)d_in[4];
    const float* w11    = (const float*)d_in[5];
    const float* w_out  = (const float*)d_in[6];
    const float* filt_d = (const float*)d_in[7];
    const float* filt_r = (const float*)d_in[8];
    float* out = (float*)d_out;

    float *xa, *xb, *y1, *y2;
    cudaGetSymbolAddress((void**)&xa, g_xa);
    cudaGetSymbolAddress((void**)&xb, g_xb);
    cudaGetSymbolAddress((void**)&y1, g_y1);
    cudaGetSymbolAddress((void**)&y2, g_y2);
    float* Lg = y1;  // y1 dead after conv_b (stream-ordered); legmix reuses it

    int l = 16434;
    {
        dim3 g((l + 127) / 128, B_);
        k_first<<<g, 128>>>(input, w_first, xa, l);
    }

    float* cur = xa;
    float* alt = xb;
    for (int i = 0; i < NB_; i++) {
        int l1 = l - 2;
        int l2 = l - 4;
        int ll = l / 6 - 1;
        int lo = l - 12;

        dim3 ga((l1 + 127) / 128, B_);
        k_conv_s<true><<<ga, 128>>>(cur, conv_a + i * CH_ * CH_ * 3, y1, l);

        dim3 gb((l2 + 127) / 128, B_);
        k_conv_s<false><<<gb, 128>>>(y1, conv_b + i * CH_ * CH_ * 3, y2, l1);

        dim3 gl((ll + TB_ - 1) / TB_, B_);
        k_legmix<<<gl, dim3(TB_, CH_)>>>(cur, lin_m + i * CH_ * MM_ * MM_,
                                         filt_d, Lg, l, ll);

        dim3 gr((lo / 6 + 127) / 128, B_ * CH_);
        k_recon<<<gr, 128>>>(Lg, filt_r, y2, alt, ll, lo);

        float* tmp = cur; cur = alt; alt = tmp;
        l = lo;
    }

    dim3 gf((LIN_ / 4 + 127) / 128, B_);
    k_final_f2<<<gf, 128>>>(cur, w11, w_out, out, l);
}

// round 9
// speedup vs baseline: 1.1512x; 1.1512x over previous
#include <cuda_runtime.h>
#include <math.h>

#define B_    32
#define INC_  10
#define LIN_  16384
#define CH_   20
#define NPOLY 12
#define MM_   6
#define NB_   4
// lengths: l0=16434 -> 16422,16410,16398,16386 (all divisible by 6)

#define BUFN 10520000  // >= 32*20*16434

__device__ float g_xa[BUFN];
__device__ float g_xb[BUFN];
__device__ float g_y1[BUFN];
__device__ float g_y2[BUFN];
__device__ float g_lg[BUFN];   // Lg now needs its own buffer (concurrent with y1)

typedef unsigned long long ull;

__device__ __forceinline__ ull pk2(float lo, float hi) {
    ull r; asm("mov.b64 %0, {%1, %2};" : "=l"(r) : "f"(lo), "f"(hi)); return r;
}
__device__ __forceinline__ void upk2(ull v, float& lo, float& hi) {
    asm("mov.b64 {%0, %1}, %2;" : "=f"(lo), "=f"(hi) : "l"(v));
}
__device__ __forceinline__ ull fma2(ull a, ull b, ull c) {
    ull d; asm("fma.rn.f32x2 %0, %1, %2, %3;" : "=l"(d) : "l"(a), "l"(b), "l"(c));
    return d;
}

// Branchless gelu: Abramowitz-Stegun 7.1.26 erf approx (|abs err| < 1.5e-7)
__device__ __forceinline__ float gelu_f(float x) {
    float z = 0.7071067811865476f * x;
    float s = fabsf(z);
    float t = __fdividef(1.0f, fmaf(0.3275911f, s, 1.0f));
    float p = fmaf(fmaf(fmaf(fmaf(1.061405429f, t, -1.453152027f),
                             t, 1.421413741f), t, -0.284496736f), t, 0.254829592f) * t;
    float e = __expf(-s * s);
    float er = fmaf(-p, e, 1.0f);
    er = copysignf(er, z);
    return 0.5f * x * (1.0f + er);
}

// ---------------------------------------------------------------------------
// First conv: input (B,10,16384) wrap-padded (25,27), conv3 -> (B,20,16434)
// ---------------------------------------------------------------------------
__global__ void __launch_bounds__(128) k_first(
    const float* __restrict__ in, const float* __restrict__ w,
    float* __restrict__ out, int lout)
{
    __shared__ float sw[CH_ * INC_ * 3];
    int tid = threadIdx.x;
    for (int i = tid; i < CH_ * INC_ * 3; i += blockDim.x) sw[i] = w[i];
    __syncthreads();

    int b = blockIdx.y;
    int t = blockIdx.x * blockDim.x + tid;
    if (t >= lout) return;

    int base = t - 25;
    int i0 = base;     if (i0 < 0) i0 += LIN_; else if (i0 >= LIN_) i0 -= LIN_;
    int i1 = base + 1; if (i1 < 0) i1 += LIN_; else if (i1 >= LIN_) i1 -= LIN_;
    int i2 = base + 2; if (i2 < 0) i2 += LIN_; else if (i2 >= LIN_) i2 -= LIN_;

    const float* inb = in + (size_t)b * INC_ * LIN_;
    float acc[CH_];
#pragma unroll
    for (int co = 0; co < CH_; co++) acc[co] = 0.f;
#pragma unroll
    for (int ci = 0; ci < INC_; ci++) {
        float v0 = inb[ci * LIN_ + i0];
        float v1 = inb[ci * LIN_ + i1];
        float v2 = inb[ci * LIN_ + i2];
#pragma unroll
        for (int co = 0; co < CH_; co++) {
            const float* wp = sw + (co * INC_ + ci) * 3;
            acc[co] = fmaf(wp[0], v0, fmaf(wp[1], v1, fmaf(wp[2], v2, acc[co])));
        }
    }
    float* ob = out + (size_t)b * CH_ * lout;
#pragma unroll
    for (int co = 0; co < CH_; co++) ob[co * lout + t] = acc[co];
}

// ---------------------------------------------------------------------------
// Shared-memory overlay for the fused kernel (conv path vs legmix path).
// ---------------------------------------------------------------------------
#define TB_ 32
struct SmemConv { float sw[CH_ * CH_ * 3]; };
struct SmemLeg  { float xs[CH_][TB_ * 6 + 6]; float fd2[MM_ * NPOLY]; float lm[CH_ * MM_ * MM_]; };
union SmemU { SmemConv c; SmemLeg l; };

// ---------------------------------------------------------------------------
// Fused launch: convA (+gelu) blocks and legmix blocks in ONE grid.
// blockIdx.x < NA            -> conv path (R2 k_conv20, VT=2, direct LDG.128)
// blockIdx.x in [NA, NA+NL)  -> legmix path (4 warps x 5 groups, lane = tau)
// Both paths latency-bound alone (~40% issue); co-residency fills slots.
// ---------------------------------------------------------------------------
__global__ void __launch_bounds__(128) k_convA_legmix(
    const float* __restrict__ x, const float* __restrict__ wa,
    const float* __restrict__ lm_g, const float* __restrict__ fd,
    float* __restrict__ y1, float* __restrict__ Lg,
    int lin, int ll, int NA)
{
    __shared__ SmemU smu;
    int tid = threadIdx.x;
    int b = blockIdx.y;

    if ((int)blockIdx.x < NA) {
        // ---------------- conv_a path (R2 k_conv20 + gelu) ----------------
        float* sw = smu.c.sw;
        for (int i = tid; i < CH_ * CH_ * 3; i += 128) sw[i] = wa[i];
        __syncthreads();

        int lout = lin - 2;
        int t0 = (blockIdx.x * 128 + tid) * 2;
        if (t0 >= lout) return;
        bool has2 = (t0 + 1 < lout);

        const float* xb = x + (size_t)b * CH_ * lin;
        float a0[CH_], a1[CH_];
#pragma unroll
        for (int co = 0; co < CH_; co++) { a0[co] = 0.f; a1[co] = 0.f; }

#pragma unroll
        for (int ci = 0; ci < CH_; ci++) {
            const float* xp = xb + ci * lin + t0;
            float v0 = xp[0], v1 = xp[1], v2 = xp[2];
            float v3 = has2 ? xp[3] : 0.f;
#pragma unroll
            for (int co = 0; co < CH_; co++) {
                const float* wp = sw + (co * CH_ + ci) * 3;
                float w0 = wp[0], w1 = wp[1], w2 = wp[2];
                a0[co] = fmaf(w0, v0, fmaf(w1, v1, fmaf(w2, v2, a0[co])));
                a1[co] = fmaf(w0, v1, fmaf(w1, v2, fmaf(w2, v3, a1[co])));
            }
        }
        float* ob = y1 + (size_t)b * CH_ * lout;
#pragma unroll
        for (int co = 0; co < CH_; co++) {
            float u0 = gelu_f(a0[co]), u1 = gelu_f(a1[co]);
            ob[co * lout + t0] = u0;
            if (has2) ob[co * lout + t0 + 1] = u1;
        }
    } else {
        // ---------------- legmix path (R2 access pattern, 128 threads) ----
        float (*xs)[TB_ * 6 + 6] = smu.l.xs;
        float* fd2 = smu.l.fd2;
        float* lm  = smu.l.lm;

        int T0 = (blockIdx.x - NA) * TB_;

        for (int i = tid; i < MM_ * NPOLY; i += 128) fd2[i] = 0.5f * fd[i];
        for (int i = tid; i < CH_ * MM_ * MM_; i += 128) lm[i] = lm_g[i];
        for (int i = tid; i < CH_ * (TB_ * 6 + 6); i += 128) {
            int ci = i / (TB_ * 6 + 6);
            int j  = i % (TB_ * 6 + 6);
            int pos = 6 * T0 + j;
            xs[ci][j] = (pos < lin) ? x[((size_t)b * CH_ + ci) * lin + pos] : 0.f;
        }
        __syncthreads();

        int wq = tid >> 5, lane = tid & 31;
        int t = T0 + lane;
        if (t >= ll) return;

#pragma unroll
        for (int gg = 0; gg < 5; gg++) {
            int g = wq * 5 + gg;   // warp-uniform group
            float v[MM_];
#pragma unroll
            for (int i = 0; i < MM_; i++) {
                int q  = 6 * g + i;
                int mi = q / CH_;
                int ci = q % CH_;
                float s = 0.f;
#pragma unroll
                for (int k = 0; k < NPOLY; k++)
                    s = fmaf(fd2[mi * NPOLY + k], xs[ci][6 * lane + k], s);
                v[i] = s;
            }
#pragma unroll
            for (int o = 0; o < MM_; o++) {
                float s = 0.f;
#pragma unroll
                for (int i = 0; i < MM_; i++)
                    s = fmaf(lm[(g * MM_ + o) * MM_ + i], v[i], s);
                int p  = 6 * g + o;
                int mo = p / CH_;
                int co = p % CH_;
                Lg[(((size_t)b * MM_ + mo) * CH_ + co) * ll + t] = s;
            }
        }
    }
}

// ---------------------------------------------------------------------------
// conv3 20->20, VALID, no gelu (R2 version — used for conv_b).
// ---------------------------------------------------------------------------
__global__ void __launch_bounds__(128) k_conv20b(
    const float* __restrict__ x, const float* __restrict__ w,
    float* __restrict__ out, int lin)
{
    __shared__ float sw[CH_ * CH_ * 3];
    int tid = threadIdx.x;
    for (int i = tid; i < CH_ * CH_ * 3; i += blockDim.x) sw[i] = w[i];
    __syncthreads();

    int lout = lin - 2;
    int b = blockIdx.y;
    int t0 = (blockIdx.x * blockDim.x + tid) * 2;
    if (t0 >= lout) return;
    bool has2 = (t0 + 1 < lout);

    const float* xb = x + (size_t)b * CH_ * lin;
    float a0[CH_], a1[CH_];
#pragma unroll
    for (int co = 0; co < CH_; co++) { a0[co] = 0.f; a1[co] = 0.f; }

#pragma unroll
    for (int ci = 0; ci < CH_; ci++) {
        const float* xp = xb + ci * lin + t0;
        float v0 = xp[0], v1 = xp[1], v2 = xp[2];
        float v3 = has2 ? xp[3] : 0.f;
#pragma unroll
        for (int co = 0; co < CH_; co++) {
            const float* wp = sw + (co * CH_ + ci) * 3;
            float w0 = wp[0], w1 = wp[1], w2 = wp[2];
            a0[co] = fmaf(w0, v0, fmaf(w1, v1, fmaf(w2, v2, a0[co])));
            a1[co] = fmaf(w0, v1, fmaf(w1, v2, fmaf(w2, v3, a1[co])));
        }
    }
    float* ob = out + (size_t)b * CH_ * lout;
#pragma unroll
    for (int co = 0; co < CH_; co++) {
        ob[co * lout + t0] = a0[co];
        if (has2) ob[co * lout + t0 + 1] = a1[co];
    }
}

// ---------------------------------------------------------------------------
// Overlap-add reconstruction + residual + gelu, VT=6 (validated R7).
// ---------------------------------------------------------------------------
__global__ void __launch_bounds__(128) k_recon(
    const float* __restrict__ Lg, const float* __restrict__ fr,
    const float* __restrict__ y2, float* __restrict__ out, int ll, int lout)
{
    __shared__ float sfr[MM_ * NPOLY];
    __shared__ float sbuf[128 * 6];

    int tid = threadIdx.x;
    if (tid < MM_ * NPOLY) sfr[tid] = fr[tid];
    __syncthreads();

    int bc = blockIdx.y;
    int b = bc / CH_, co = bc % CH_;
    int nu = lout / 6;

    int u = blockIdx.x * 128 + tid;
    if (u < nu) {
        int t0 = u + 1;
        const float* Lo = Lg + (((size_t)b * MM_) * CH_ + co) * ll;
        size_t mstride = (size_t)CH_ * ll;
        float rec[6];
#pragma unroll
        for (int e = 0; e < 6; e++) rec[e] = 0.f;
#pragma unroll
        for (int m = 0; m < MM_; m++) {
            float uc = Lo[m * mstride + t0];
            float up = Lo[m * mstride + t0 - 1];
#pragma unroll
            for (int e = 0; e < 6; e++) {
                rec[e] = fmaf(uc, sfr[m * NPOLY + e],     rec[e]);
                rec[e] = fmaf(up, sfr[m * NPOLY + e + 6], rec[e]);
            }
        }
#pragma unroll
        for (int e = 0; e < 6; e++) sbuf[6 * tid + e] = rec[e];
    }
    __syncthreads();

    int Tbase = blockIdx.x * 768;
    int liny2 = lout + 8;
    const float* y2r = y2 + (size_t)bc * liny2;
    float* outr = out + (size_t)bc * lout;
#pragma unroll
    for (int e2 = 0; e2 < 6; e2++) {
        int idx = tid + 128 * e2;
        int t = Tbase + idx;
        if (t < lout)
            outr[t] = gelu_f(sbuf[idx] + y2r[t + 4]);
    }
}

// ---------------------------------------------------------------------------
// Final 20->128(gelu)->1 with f32x2, VT=4 (validated).
// ---------------------------------------------------------------------------
__global__ void __launch_bounds__(128) k_final_f2(
    const float* __restrict__ x, const float* __restrict__ w11,
    const float* __restrict__ w_out, float* __restrict__ out, int lin)
{
    __shared__ __align__(16) float2 swd[128 * CH_];
    __shared__ float so[128];
    int tid = threadIdx.x;
    for (int i = tid; i < 128 * CH_; i += 128) {
        float v = w11[i];
        swd[i] = make_float2(v, v);
    }
    if (tid < 128) so[tid] = w_out[tid];
    __syncthreads();

    int b = blockIdx.y;
    int t0 = (blockIdx.x * 128 + tid) * 4;
    if (t0 >= LIN_) return;

    const float* xb = x + (size_t)b * CH_ * lin + t0;
    ull xv01[CH_], xv23[CH_];
#pragma unroll
    for (int c = 0; c < CH_; c++) {
        const float* xp = xb + c * lin;
        xv01[c] = pk2(xp[0], xp[1]);
        xv23[c] = pk2(xp[2], xp[3]);
    }

    ull zero = pk2(0.f, 0.f);
    ull acc01 = zero, acc23 = zero;
#pragma unroll 2
    for (int o = 0; o < 128; o++) {
        ull h01 = zero, h23 = zero;
#pragma unroll
        for (int c = 0; c < CH_; c++) {
            ull wv = *(const ull*)&swd[o * CH_ + c];
            h01 = fma2(wv, xv01[c], h01);
            h23 = fma2(wv, xv23[c], h23);
        }
        float h0, h1, h2, h3;
        upk2(h01, h0, h1); upk2(h23, h2, h3);
        float ov = so[o];
        ull ov2 = pk2(ov, ov);
        acc01 = fma2(ov2, pk2(gelu_f(h0), gelu_f(h1)), acc01);
        acc23 = fma2(ov2, pk2(gelu_f(h2), gelu_f(h3)), acc23);
    }
    float r0, r1, r2, r3;
    upk2(acc01, r0, r1); upk2(acc23, r2, r3);
    float4* op = (float4*)&out[(size_t)b * LIN_ + t0];
    *op = make_float4(r0, r1, r2, r3);
}

// ---------------------------------------------------------------------------
extern "C" void kernel_launch(void* const* d_in, const int* in_sizes, int n_in,
                              void* d_out, int out_size)
{
    const float* input  = (const float*)d_in[0];
    const float* w_first= (const float*)d_in[1];
    const float* conv_a = (const float*)d_in[2];
    const float* conv_b = (const float*)d_in[3];
    const float* lin_m  = (const float*)d_in[4];
    const float* w11    = (const float*)d_in[5];
    const float* w_out  = (const float*)d_in[6];
    const float* filt_d = (const float*)d_in[7];
    const float* filt_r = (const float*)d_in[8];
    float* out = (float*)d_out;

    float *xa, *xb, *y1, *y2, *Lg;
    cudaGetSymbolAddress((void**)&xa, g_xa);
    cudaGetSymbolAddress((void**)&xb, g_xb);
    cudaGetSymbolAddress((void**)&y1, g_y1);
    cudaGetSymbolAddress((void**)&y2, g_y2);
    cudaGetSymbolAddress((void**)&Lg, g_lg);

    int l = 16434;
    {
        dim3 g((l + 127) / 128, B_);
        k_first<<<g, 128>>>(input, w_first, xa, l);
    }

    float* cur = xa;
    float* alt = xb;
    for (int i = 0; i < NB_; i++) {
        int l1 = l - 2;
        int l2 = l - 4;
        int ll = l / 6 - 1;
        int lo = l - 12;

        int NA = (l1 + 255) / 256;      // conv_a blocks (VT=2, 128 thr)
        int NL = (ll + TB_ - 1) / TB_;  // legmix blocks
        dim3 gf(NA + NL, B_);
        k_convA_legmix<<<gf, 128>>>(cur, conv_a + i * CH_ * CH_ * 3,
                                    lin_m + i * CH_ * MM_ * MM_, filt_d,
                                    y1, Lg, l, ll, NA);

        dim3 gb((l2 + 255) / 256, B_);
        k_conv20b<<<gb, 128>>>(y1, conv_b + i * CH_ * CH_ * 3, y2, l1);

        dim3 gr((lo / 6 + 127) / 128, B_ * CH_);
        k_recon<<<gr, 128>>>(Lg, filt_r, y2, alt, ll, lo);

        float* tmp = cur; cur = alt; alt = tmp;
        l = lo;
    }

    dim3 gfin((LIN_ / 4 + 127) / 128, B_);
    k_final_f2<<<gfin, 128>>>(cur, w11, w_out, out, l);
}